// round 4
// baseline (speedup 1.0000x reference)
#include <cuda_runtime.h>
#include <cuda_bf16.h>
#include <cstdint>

// ---------------------------------------------------------------------------
// EvolveGCNLayer: out = relu(segment_sum( (h@W)[src] * ew , dst ))
// Linearity: segment_sum((h@W)[src]*ew,dst) == segment_sum(h[src]*ew,dst) @ W
// Pipeline:
//   (d) detect index dtype (int32 vs int64 — JAX x64 ambiguity)
//   (0) zero histogram   (1) histogram of dst   (2) scan -> CSR offsets
//   (3) permute edges    (4) per-dst gather-reduce -> g_agg (no atomics)
//   (5) 3xTF32 tensor-core GEMM g_agg @ W -> out, ReLU fused
// ---------------------------------------------------------------------------

#define D 512
#define MAX_NODES 100000
#define MAX_EDGES 1600000

__device__ float g_agg[(size_t)MAX_NODES * D];   // aggregated features (204.8 MB)
__device__ int   g_count[MAX_NODES];             // histogram
__device__ int   g_cursor[MAX_NODES];            // scatter cursors
__device__ int   g_offset[MAX_NODES + 1];        // CSR offsets
__device__ int   g_psrc[MAX_EDGES];              // src node per CSR slot
__device__ float g_pw[MAX_EDGES];                // edge weight per CSR slot
__device__ int   g_idx_is64;                     // 1 if src/dst are int64

// ---------------------- (d) index dtype detection --------------------------
// int64 indices are all < 100000 < 2^32. int32 data read as u64 packs two
// indices: value >= 2^32 whenever the odd-position index != 0.
__global__ __launch_bounds__(512) void detect_kernel(const void* __restrict__ src,
                                                     int n_edges) {
    __shared__ int flag;
    if (threadIdx.x == 0) flag = 1;
    __syncthreads();
    const unsigned long long* p = (const unsigned long long*)src;
    int n = n_edges / 2;              // safe u64 word count for BOTH dtypes
    if (n > 512) n = 512;
    if ((int)threadIdx.x < n && p[threadIdx.x] >= 4294967296ULL) flag = 0;
    __syncthreads();
    if (threadIdx.x == 0) g_idx_is64 = flag;
}

__device__ __forceinline__ int load_idx(const void* p, int i, int is64) {
    return is64 ? (int)((const long long*)p)[i] : ((const int*)p)[i];
}

// ---------------------- (0) zero histogram ---------------------------------
__global__ __launch_bounds__(256) void zero_counts_kernel(int n) {
    int i = blockIdx.x * blockDim.x + threadIdx.x;
    if (i < n) g_count[i] = 0;
}

// ---------------------- (1) histogram of dst -------------------------------
__global__ __launch_bounds__(256) void hist_kernel(
    const void* __restrict__ dst, int n_edges)
{
    const int is64 = g_idx_is64;
    int i = blockIdx.x * blockDim.x + threadIdx.x;
    int stride = gridDim.x * blockDim.x;
    for (; i < n_edges; i += stride)
        atomicAdd(&g_count[load_idx(dst, i, is64)], 1);
}

// ---------------------- (2) single-block exclusive scan --------------------
__global__ __launch_bounds__(1024) void scan_kernel(int n) {
    __shared__ int warp_sums[32];
    __shared__ int carry_sm;
    const int tid  = threadIdx.x;
    const int lane = tid & 31;
    const int wid  = tid >> 5;
    if (tid == 0) carry_sm = 0;
    __syncthreads();

    for (int base = 0; base < n; base += 1024) {
        const int idx = base + tid;
        int v = (idx < n) ? g_count[idx] : 0;

        int s = v;
        #pragma unroll
        for (int off = 1; off < 32; off <<= 1) {
            int t = __shfl_up_sync(0xffffffffu, s, off);
            if (lane >= off) s += t;
        }
        if (lane == 31) warp_sums[wid] = s;
        __syncthreads();

        if (wid == 0) {
            int ws = warp_sums[lane];
            #pragma unroll
            for (int off = 1; off < 32; off <<= 1) {
                int t = __shfl_up_sync(0xffffffffu, ws, off);
                if (lane >= off) ws += t;
            }
            warp_sums[lane] = ws;
        }
        __syncthreads();

        const int warp_off = (wid > 0) ? warp_sums[wid - 1] : 0;
        const int excl = carry_sm + warp_off + s - v;
        if (idx < n) {
            g_offset[idx] = excl;
            g_cursor[idx] = excl;
        }
        __syncthreads();
        if (tid == 0) carry_sm += warp_sums[31];
        __syncthreads();
    }
    if (tid == 0) g_offset[n] = carry_sm;
}

// ---------------------- (3) permute edges into CSR order -------------------
__global__ __launch_bounds__(256) void permute_kernel(
    const float* __restrict__ ew,
    const void*  __restrict__ src,
    const void*  __restrict__ dst,
    int n_edges)
{
    const int is64 = g_idx_is64;
    int i = blockIdx.x * blockDim.x + threadIdx.x;
    int stride = gridDim.x * blockDim.x;
    for (; i < n_edges; i += stride) {
        const int d = load_idx(dst, i, is64);
        const int pos = atomicAdd(&g_cursor[d], 1);
        g_psrc[pos] = load_idx(src, i, is64);
        g_pw[pos]   = ew[i];
    }
}

// ---------------------- (4) gather-reduce per destination ------------------
__global__ __launch_bounds__(128) void gather_kernel(
    const float* __restrict__ h, int n_nodes)
{
    const int node = blockIdx.x;
    if (node >= n_nodes) return;
    const int tid = threadIdx.x;

    const int beg = g_offset[node];
    const int end = g_offset[node + 1];

    const float4* __restrict__ h4 = (const float4*)h;

    float4 acc0 = make_float4(0.f, 0.f, 0.f, 0.f);
    float4 acc1 = make_float4(0.f, 0.f, 0.f, 0.f);

    int j = beg;
    for (; j + 1 < end; j += 2) {
        const int   s0 = g_psrc[j],     s1 = g_psrc[j + 1];
        const float w0 = g_pw[j],       w1 = g_pw[j + 1];
        float4 v0 = h4[(long long)s0 * 128 + tid];
        float4 v1 = h4[(long long)s1 * 128 + tid];
        acc0.x += v0.x * w0; acc0.y += v0.y * w0;
        acc0.z += v0.z * w0; acc0.w += v0.w * w0;
        acc1.x += v1.x * w1; acc1.y += v1.y * w1;
        acc1.z += v1.z * w1; acc1.w += v1.w * w1;
    }
    if (j < end) {
        const int   s = g_psrc[j];
        const float w = g_pw[j];
        float4 v = h4[(long long)s * 128 + tid];
        acc0.x += v.x * w; acc0.y += v.y * w;
        acc0.z += v.z * w; acc0.w += v.w * w;
    }
    acc0.x += acc1.x; acc0.y += acc1.y;
    acc0.z += acc1.z; acc0.w += acc1.w;

    ((float4*)g_agg)[(long long)node * 128 + tid] = acc0;
}

// ---------------------- (5) 3xTF32 tensor GEMM + fused ReLU ----------------
// C = relu(g_agg @ W). BM=128, BN=128, BK=16. 256 threads = 8 warps (2x4),
// warp tile 64x32, mma.m16n8k8 tf32. Split precision: X = Xh + Xl (tf32 each),
// D = Ah*Bh + Ah*Bl + Al*Bh  (Al*Bl ~ 2^-22, dropped).
#define BM 128
#define BN 128
#define BK 16

// smem strides chosen for conflict-free fragment loads:
//   A [m][k] stride 20: bank = (20g+t)%32 -> all 32 lanes distinct
//   B [k][n] stride 136: bank = (8t+g)%32 -> all 32 lanes distinct
#define ASTR 20
#define BSTR 136

__device__ __forceinline__ void split_tf32(float x, float& hi, float& lo) {
    unsigned hbits, lbits;
    asm("cvt.rna.tf32.f32 %0, %1;" : "=r"(hbits) : "f"(x));
    float hf = __uint_as_float(hbits);
    float r = x - hf;                       // exact in fp32
    asm("cvt.rna.tf32.f32 %0, %1;" : "=r"(lbits) : "f"(r));
    hi = hf;
    lo = __uint_as_float(lbits);
}

__device__ __forceinline__ void mma_tf32(float* c, const unsigned* a,
                                         const unsigned* b) {
    asm volatile(
        "mma.sync.aligned.m16n8k8.row.col.f32.tf32.tf32.f32 "
        "{%0,%1,%2,%3}, {%4,%5,%6,%7}, {%8,%9}, {%0,%1,%2,%3};"
        : "+f"(c[0]), "+f"(c[1]), "+f"(c[2]), "+f"(c[3])
        : "r"(a[0]), "r"(a[1]), "r"(a[2]), "r"(a[3]),
          "r"(b[0]), "r"(b[1]));
}

__global__ __launch_bounds__(256) void gemm_relu_kernel(
    const float* __restrict__ B,   // W [512, 512] row-major
    float* __restrict__ C,         // out [M, 512]
    int M)
{
    __shared__ float As_hi[BM][ASTR], As_lo[BM][ASTR];  // 10240 B each
    __shared__ float Bs_hi[BK][BSTR], Bs_lo[BK][BSTR];  //  8704 B each

    const int bcol   = blockIdx.x;         // 0..3
    const int m_base = blockIdx.y * BM;
    const int tid    = threadIdx.x;
    const int wid    = tid >> 5;
    const int lane   = tid & 31;
    const int g      = lane >> 2;          // groupID 0..7
    const int t      = lane & 3;           // threadInGroup 0..3

    const int wm = wid & 1;                // 0..1 : 64-row half
    const int wn = wid >> 1;               // 0..3 : 32-col strip

    const float* Ab = g_agg + (long long)m_base * D;
    const float* Bb = B + (long long)bcol * BN;

    float acc[4][4][4];                    // [mt][nt][4]
    #pragma unroll
    for (int i = 0; i < 4; i++)
        #pragma unroll
        for (int j = 0; j < 4; j++)
            #pragma unroll
            for (int r = 0; r < 4; r++) acc[i][j][r] = 0.0f;

    for (int k0 = 0; k0 < D; k0 += BK) {
        // ---- stage A tile [BM x BK] with hi/lo split ----
        #pragma unroll
        for (int it = 0; it < 2; it++) {
            const int f4  = tid + it * 256;    // 0..511
            const int row = f4 >> 2;           // 0..127
            const int c4  = (f4 & 3) * 4;      // 0,4,8,12
            float4 v = make_float4(0.f, 0.f, 0.f, 0.f);
            if (m_base + row < M)
                v = *(const float4*)(Ab + (long long)row * D + k0 + c4);
            float h0, l0, h1, l1, h2, l2, h3, l3;
            split_tf32(v.x, h0, l0); split_tf32(v.y, h1, l1);
            split_tf32(v.z, h2, l2); split_tf32(v.w, h3, l3);
            *(float4*)&As_hi[row][c4] = make_float4(h0, h1, h2, h3);
            *(float4*)&As_lo[row][c4] = make_float4(l0, l1, l2, l3);
        }
        // ---- stage B tile [BK x BN] with hi/lo split ----
        #pragma unroll
        for (int it = 0; it < 2; it++) {
            const int f4  = tid + it * 256;    // 0..511
            const int row = f4 >> 5;           // 0..15
            const int c4  = (f4 & 31) * 4;     // 0..124 step 4
            float4 v = *(const float4*)(Bb + (long long)(k0 + row) * D + c4);
            float h0, l0, h1, l1, h2, l2, h3, l3;
            split_tf32(v.x, h0, l0); split_tf32(v.y, h1, l1);
            split_tf32(v.z, h2, l2); split_tf32(v.w, h3, l3);
            *(float4*)&Bs_hi[row][c4] = make_float4(h0, h1, h2, h3);
            *(float4*)&Bs_lo[row][c4] = make_float4(l0, l1, l2, l3);
        }
        __syncthreads();

        // ---- two k-steps of 8 ----
        #pragma unroll
        for (int ks = 0; ks < BK; ks += 8) {
            // B fragments for this warp's 4 n-tiles
            unsigned bh[4][2], bl[4][2];
            #pragma unroll
            for (int nt = 0; nt < 4; nt++) {
                const int n = wn * 32 + nt * 8 + g;
                bh[nt][0] = __float_as_uint(Bs_hi[ks + t][n]);
                bh[nt][1] = __float_as_uint(Bs_hi[ks + t + 4][n]);
                bl[nt][0] = __float_as_uint(Bs_lo[ks + t][n]);
                bl[nt][1] = __float_as_uint(Bs_lo[ks + t + 4][n]);
            }
            #pragma unroll
            for (int mt = 0; mt < 4; mt++) {
                const int r0 = wm * 64 + mt * 16 + g;
                unsigned ah[4], al[4];
                ah[0] = __float_as_uint(As_hi[r0][ks + t]);
                ah[1] = __float_as_uint(As_hi[r0 + 8][ks + t]);
                ah[2] = __float_as_uint(As_hi[r0][ks + t + 4]);
                ah[3] = __float_as_uint(As_hi[r0 + 8][ks + t + 4]);
                al[0] = __float_as_uint(As_lo[r0][ks + t]);
                al[1] = __float_as_uint(As_lo[r0 + 8][ks + t]);
                al[2] = __float_as_uint(As_lo[r0][ks + t + 4]);
                al[3] = __float_as_uint(As_lo[r0 + 8][ks + t + 4]);
                #pragma unroll
                for (int nt = 0; nt < 4; nt++) {
                    mma_tf32(acc[mt][nt], ah, bh[nt]);
                    mma_tf32(acc[mt][nt], ah, bl[nt]);
                    mma_tf32(acc[mt][nt], al, bh[nt]);
                }
            }
        }
        __syncthreads();
    }

    // ---- epilogue: ReLU + float2 stores ----
    #pragma unroll
    for (int mt = 0; mt < 4; mt++) {
        const int row0 = m_base + wm * 64 + mt * 16 + g;
        const int row1 = row0 + 8;
        #pragma unroll
        for (int nt = 0; nt < 4; nt++) {
            const int col = bcol * BN + wn * 32 + nt * 8 + 2 * t;
            if (row0 < M) {
                float2 v = make_float2(fmaxf(acc[mt][nt][0], 0.f),
                                       fmaxf(acc[mt][nt][1], 0.f));
                *(float2*)(C + (long long)row0 * D + col) = v;
            }
            if (row1 < M) {
                float2 v = make_float2(fmaxf(acc[mt][nt][2], 0.f),
                                       fmaxf(acc[mt][nt][3], 0.f));
                *(float2*)(C + (long long)row1 * D + col) = v;
            }
        }
    }
}

// ---------------------------------------------------------------------------
extern "C" void kernel_launch(void* const* d_in, const int* in_sizes, int n_in,
                              void* d_out, int out_size)
{
    const float* h   = (const float*)d_in[0];
    const float* W   = (const float*)d_in[1];
    const float* ew  = (const float*)d_in[2];
    const void*  src = d_in[3];
    const void*  dst = d_in[4];
    float* out = (float*)d_out;

    const int M = in_sizes[0] / D;   // nodes
    const int E = in_sizes[2];       // edges (ew is unambiguous f32)

    // (d) detect whether src/dst are int32 or int64
    detect_kernel<<<1, 512>>>(src, E);

    // (0) zero histogram
    zero_counts_kernel<<<(M + 255) / 256, 256>>>(M);

    // (1) histogram of dst
    hist_kernel<<<1184, 256>>>(dst, E);

    // (2) exclusive scan -> offsets + cursors
    scan_kernel<<<1, 1024>>>(M);

    // (3) permute edges into CSR-by-dst
    permute_kernel<<<1184, 256>>>(ew, src, dst, E);

    // (4) gather-reduce: g_agg[n] = sum_{e: dst=n} h[src_e] * ew_e
    gather_kernel<<<M, 128>>>(h, M);

    // (5) out = relu(g_agg @ W) — 3xTF32 tensor cores, writes every element
    dim3 ggrid(D / BN, (M + BM - 1) / BM);
    gemm_relu_kernel<<<ggrid, 256>>>(W, out, M);
}

// round 5
// speedup vs baseline: 1.0418x; 1.0418x over previous
#include <cuda_runtime.h>
#include <cuda_bf16.h>
#include <cstdint>

// ---------------------------------------------------------------------------
// EvolveGCNLayer: out = relu(segment_sum( (h@W)[src] * ew , dst ))
// Linearity: segment_sum((h@W)[src]*ew,dst) == segment_sum(h[src]*ew,dst) @ W
// Pipeline:
//   (d) detect index dtype     (0) zero histogram    (1) histogram of dst
//   (2) 3-phase parallel scan  (3) permute edges -> CSR
//   (4) column-tiled gather-reduce (h L2-resident per tile)
//   (5) 3xTF32 tensor-core GEMM g_agg @ W -> out, ReLU fused
// ---------------------------------------------------------------------------

#define D 512
#define MAX_NODES 100000
#define MAX_EDGES 1600000

__device__ float g_agg[(size_t)MAX_NODES * D];   // aggregated features (204.8 MB)
__device__ int   g_count[MAX_NODES];             // histogram
__device__ int   g_cursor[MAX_NODES];            // scatter cursors
__device__ int   g_offset[MAX_NODES + 1];        // CSR offsets
__device__ int   g_psrc[MAX_EDGES];              // src node per CSR slot
__device__ float g_pw[MAX_EDGES];                // edge weight per CSR slot
__device__ int   g_idx_is64;                     // 1 if src/dst are int64
__device__ int   g_bsum[64];                     // per-block scan sums
__device__ int   g_boff[64];                     // per-block scan offsets
__device__ float g_Wh[D * D];                    // W split: tf32 hi
__device__ float g_Wl[D * D];                    // W split: tf32 lo

// ---------------------- (d) index dtype detection --------------------------
__global__ __launch_bounds__(512) void detect_kernel(const void* __restrict__ src,
                                                     int n_edges) {
    __shared__ int flag;
    if (threadIdx.x == 0) flag = 1;
    __syncthreads();
    const unsigned long long* p = (const unsigned long long*)src;
    int n = n_edges / 2;              // safe u64 word count for BOTH dtypes
    if (n > 512) n = 512;
    if ((int)threadIdx.x < n && p[threadIdx.x] >= 4294967296ULL) flag = 0;
    __syncthreads();
    if (threadIdx.x == 0) g_idx_is64 = flag;
}

__device__ __forceinline__ int load_idx(const void* p, int i, int is64) {
    return is64 ? (int)((const long long*)p)[i] : ((const int*)p)[i];
}

// ---------------------- (0) zero histogram ---------------------------------
__global__ __launch_bounds__(256) void zero_counts_kernel(int n) {
    int i = blockIdx.x * blockDim.x + threadIdx.x;
    if (i < n) g_count[i] = 0;
}

// ---------------------- (1) histogram of dst -------------------------------
__global__ __launch_bounds__(256) void hist_kernel(
    const void* __restrict__ dst, int n_edges)
{
    const int is64 = g_idx_is64;
    int i = blockIdx.x * blockDim.x + threadIdx.x;
    int stride = gridDim.x * blockDim.x;
    for (; i < n_edges; i += stride)
        atomicAdd(&g_count[load_idx(dst, i, is64)], 1);
}

// ---------------------- (2) 3-phase parallel exclusive scan ----------------
#define SCAN_CHUNK 4096          // 1024 threads x 4 elems

// phase A: local scan per 4096-chunk, write local-exclusive + chunk sum
__global__ __launch_bounds__(1024) void scan_block_kernel(int n) {
    __shared__ int warp_sums[32];
    const int tid  = threadIdx.x;
    const int lane = tid & 31;
    const int wid  = tid >> 5;
    const int base = blockIdx.x * SCAN_CHUNK + tid * 4;

    int v0 = 0, v1 = 0, v2 = 0, v3 = 0;
    if (base + 3 < n) {
        int4 q = *(const int4*)&g_count[base];
        v0 = q.x; v1 = q.y; v2 = q.z; v3 = q.w;
    } else {
        if (base + 0 < n) v0 = g_count[base + 0];
        if (base + 1 < n) v1 = g_count[base + 1];
        if (base + 2 < n) v2 = g_count[base + 2];
        if (base + 3 < n) v3 = g_count[base + 3];
    }
    const int tsum = v0 + v1 + v2 + v3;

    // inclusive warp scan of tsum
    int s = tsum;
    #pragma unroll
    for (int off = 1; off < 32; off <<= 1) {
        int t = __shfl_up_sync(0xffffffffu, s, off);
        if (lane >= off) s += t;
    }
    if (lane == 31) warp_sums[wid] = s;
    __syncthreads();
    if (wid == 0) {
        int ws = warp_sums[lane];
        #pragma unroll
        for (int off = 1; off < 32; off <<= 1) {
            int t = __shfl_up_sync(0xffffffffu, ws, off);
            if (lane >= off) ws += t;
        }
        warp_sums[lane] = ws;
    }
    __syncthreads();

    const int warp_off = (wid > 0) ? warp_sums[wid - 1] : 0;
    int excl = warp_off + s - tsum;      // local exclusive for this thread

    if (base + 0 < n) g_offset[base + 0] = excl;
    if (base + 1 < n) g_offset[base + 1] = excl + v0;
    if (base + 2 < n) g_offset[base + 2] = excl + v0 + v1;
    if (base + 3 < n) g_offset[base + 3] = excl + v0 + v1 + v2;

    if (tid == 1023) g_bsum[blockIdx.x] = warp_sums[31];
}

// phase B: 1-warp exclusive scan of chunk sums (nb <= 32)
__global__ __launch_bounds__(32) void scan_tops_kernel(int nb) {
    const int lane = threadIdx.x;
    int v = (lane < nb) ? g_bsum[lane] : 0;
    int s = v;
    #pragma unroll
    for (int off = 1; off < 32; off <<= 1) {
        int t = __shfl_up_sync(0xffffffffu, s, off);
        if (lane >= off) s += t;
    }
    if (lane < nb) g_boff[lane] = s - v;
}

// phase C: add chunk offset, emit cursors + sentinel
__global__ __launch_bounds__(1024) void scan_add_kernel(int n, int total) {
    const int i = blockIdx.x * blockDim.x + threadIdx.x;
    if (i < n) {
        const int o = g_offset[i] + g_boff[i / SCAN_CHUNK];
        g_offset[i] = o;
        g_cursor[i] = o;
    }
    if (i == 0) g_offset[n] = total;
}

// ---------------------- (3) permute edges into CSR order -------------------
__global__ __launch_bounds__(256) void permute_kernel(
    const float* __restrict__ ew,
    const void*  __restrict__ src,
    const void*  __restrict__ dst,
    int n_edges)
{
    const int is64 = g_idx_is64;
    int i = blockIdx.x * blockDim.x + threadIdx.x;
    int stride = gridDim.x * blockDim.x;
    for (; i < n_edges; i += stride) {
        const int d = load_idx(dst, i, is64);
        const int pos = atomicAdd(&g_cursor[d], 1);
        g_psrc[pos] = load_idx(src, i, is64);
        g_pw[pos]   = ew[i];
    }
}

// ---------------------- (4) column-tiled gather-reduce ---------------------
// Tile D into 4 slices of 128 floats (32 float4). Per-pass h working set:
// 100k x 512B = 51.2MB -> L2-resident. One warp per (node, tile); lane owns
// one float4 of the slice. 4-deep unroll for MLP.
__global__ __launch_bounds__(256) void gather_kernel(
    const float* __restrict__ h, int n_nodes)
{
    const int warp_in_blk = threadIdx.x >> 5;
    const int lane        = threadIdx.x & 31;
    const int node        = blockIdx.x * 8 + warp_in_blk;
    const int tile        = blockIdx.y;              // 0..3
    if (node >= n_nodes) return;

    const int beg = g_offset[node];
    const int end = g_offset[node + 1];

    const float4* __restrict__ h4 = (const float4*)h + tile * 32 + lane;

    float4 a0 = make_float4(0.f, 0.f, 0.f, 0.f);
    float4 a1 = make_float4(0.f, 0.f, 0.f, 0.f);
    float4 a2 = make_float4(0.f, 0.f, 0.f, 0.f);
    float4 a3 = make_float4(0.f, 0.f, 0.f, 0.f);

    int j = beg;
    for (; j + 3 < end; j += 4) {
        const int   s0 = g_psrc[j],     s1 = g_psrc[j + 1];
        const int   s2 = g_psrc[j + 2], s3 = g_psrc[j + 3];
        const float w0 = g_pw[j],       w1 = g_pw[j + 1];
        const float w2 = g_pw[j + 2],   w3 = g_pw[j + 3];
        float4 v0 = h4[(long long)s0 * 128];
        float4 v1 = h4[(long long)s1 * 128];
        float4 v2 = h4[(long long)s2 * 128];
        float4 v3 = h4[(long long)s3 * 128];
        a0.x += v0.x * w0; a0.y += v0.y * w0; a0.z += v0.z * w0; a0.w += v0.w * w0;
        a1.x += v1.x * w1; a1.y += v1.y * w1; a1.z += v1.z * w1; a1.w += v1.w * w1;
        a2.x += v2.x * w2; a2.y += v2.y * w2; a2.z += v2.z * w2; a2.w += v2.w * w2;
        a3.x += v3.x * w3; a3.y += v3.y * w3; a3.z += v3.z * w3; a3.w += v3.w * w3;
    }
    for (; j < end; j++) {
        const int   s = g_psrc[j];
        const float w = g_pw[j];
        float4 v = h4[(long long)s * 128];
        a0.x += v.x * w; a0.y += v.y * w; a0.z += v.z * w; a0.w += v.w * w;
    }
    a0.x += a1.x + a2.x + a3.x;
    a0.y += a1.y + a2.y + a3.y;
    a0.z += a1.z + a2.z + a3.z;
    a0.w += a1.w + a2.w + a3.w;

    ((float4*)g_agg)[(long long)node * 128 + tile * 32 + lane] = a0;
}

// ---------------------- W split (once per call, 1MB) -----------------------
__device__ __forceinline__ void split_tf32(float x, float& hi, float& lo) {
    unsigned hbits, lbits;
    asm("cvt.rna.tf32.f32 %0, %1;" : "=r"(hbits) : "f"(x));
    float hf = __uint_as_float(hbits);
    float r = x - hf;                       // exact in fp32
    asm("cvt.rna.tf32.f32 %0, %1;" : "=r"(lbits) : "f"(r));
    hi = hf;
    lo = __uint_as_float(lbits);
}

__global__ __launch_bounds__(256) void wsplit_kernel(const float* __restrict__ W) {
    const int i = blockIdx.x * blockDim.x + threadIdx.x;
    if (i < D * D) {
        float hi, lo;
        split_tf32(W[i], hi, lo);
        g_Wh[i] = hi;
        g_Wl[i] = lo;
    }
}

// ---------------------- (5) 3xTF32 tensor GEMM + fused ReLU ----------------
// C = relu(g_agg @ W). BM=128, BN=128, BK=16. 256 threads = 8 warps (2x4),
// warp tile 64x32, mma.m16n8k8 tf32. D = Ah*Bh + Ah*Bl + Al*Bh.
#define BM 128
#define BN 128
#define BK 16
#define ASTR 20     // bank=(20g+t)%32 all distinct
#define BSTR 136    // bank=(8t+g)%32 all distinct

__device__ __forceinline__ void mma_tf32(float* c, const unsigned* a,
                                         const unsigned* b) {
    asm volatile(
        "mma.sync.aligned.m16n8k8.row.col.f32.tf32.tf32.f32 "
        "{%0,%1,%2,%3}, {%4,%5,%6,%7}, {%8,%9}, {%0,%1,%2,%3};"
        : "+f"(c[0]), "+f"(c[1]), "+f"(c[2]), "+f"(c[3])
        : "r"(a[0]), "r"(a[1]), "r"(a[2]), "r"(a[3]),
          "r"(b[0]), "r"(b[1]));
}

__global__ __launch_bounds__(256) void gemm_relu_kernel(
    float* __restrict__ C,         // out [M, 512]
    int M)
{
    __shared__ float As_hi[BM][ASTR], As_lo[BM][ASTR];
    __shared__ float Bs_hi[BK][BSTR], Bs_lo[BK][BSTR];

    const int bcol   = blockIdx.x;         // 0..3
    const int m_base = blockIdx.y * BM;
    const int tid    = threadIdx.x;
    const int wid    = tid >> 5;
    const int lane   = tid & 31;
    const int g      = lane >> 2;          // groupID 0..7
    const int t      = lane & 3;           // threadInGroup 0..3

    const int wm = wid & 1;                // 0..1 : 64-row half
    const int wn = wid >> 1;               // 0..3 : 32-col strip

    const float* Ab  = g_agg + (long long)m_base * D;
    const float* Bbh = g_Wh + bcol * BN;
    const float* Bbl = g_Wl + bcol * BN;

    float acc[4][4][4];
    #pragma unroll
    for (int i = 0; i < 4; i++)
        #pragma unroll
        for (int j = 0; j < 4; j++)
            #pragma unroll
            for (int r = 0; r < 4; r++) acc[i][j][r] = 0.0f;

    for (int k0 = 0; k0 < D; k0 += BK) {
        // ---- stage A tile [BM x BK] with hi/lo split ----
        #pragma unroll
        for (int it = 0; it < 2; it++) {
            const int f4  = tid + it * 256;    // 0..511
            const int row = f4 >> 2;           // 0..127
            const int c4  = (f4 & 3) * 4;      // 0,4,8,12
            float4 v = make_float4(0.f, 0.f, 0.f, 0.f);
            if (m_base + row < M)
                v = *(const float4*)(Ab + (long long)row * D + k0 + c4);
            float h0, l0, h1, l1, h2, l2, h3, l3;
            split_tf32(v.x, h0, l0); split_tf32(v.y, h1, l1);
            split_tf32(v.z, h2, l2); split_tf32(v.w, h3, l3);
            *(float4*)&As_hi[row][c4] = make_float4(h0, h1, h2, h3);
            *(float4*)&As_lo[row][c4] = make_float4(l0, l1, l2, l3);
        }
        // ---- stage B tile [BK x BN] from pre-split Wh/Wl ----
        #pragma unroll
        for (int it = 0; it < 2; it++) {
            const int f4  = tid + it * 256;    // 0..511
            const int row = f4 >> 5;           // 0..15
            const int c4  = (f4 & 31) * 4;     // 0..124 step 4
            const long long off = (long long)(k0 + row) * D + c4;
            *(float4*)&Bs_hi[row][c4] = *(const float4*)(Bbh + off);
            *(float4*)&Bs_lo[row][c4] = *(const float4*)(Bbl + off);
        }
        __syncthreads();

        // ---- two k-steps of 8 ----
        #pragma unroll
        for (int ks = 0; ks < BK; ks += 8) {
            unsigned bh[4][2], bl[4][2];
            #pragma unroll
            for (int nt = 0; nt < 4; nt++) {
                const int n = wn * 32 + nt * 8 + g;
                bh[nt][0] = __float_as_uint(Bs_hi[ks + t][n]);
                bh[nt][1] = __float_as_uint(Bs_hi[ks + t + 4][n]);
                bl[nt][0] = __float_as_uint(Bs_lo[ks + t][n]);
                bl[nt][1] = __float_as_uint(Bs_lo[ks + t + 4][n]);
            }
            #pragma unroll
            for (int mt = 0; mt < 4; mt++) {
                const int r0 = wm * 64 + mt * 16 + g;
                unsigned ah[4], al[4];
                ah[0] = __float_as_uint(As_hi[r0][ks + t]);
                ah[1] = __float_as_uint(As_hi[r0 + 8][ks + t]);
                ah[2] = __float_as_uint(As_hi[r0][ks + t + 4]);
                ah[3] = __float_as_uint(As_hi[r0 + 8][ks + t + 4]);
                al[0] = __float_as_uint(As_lo[r0][ks + t]);
                al[1] = __float_as_uint(As_lo[r0 + 8][ks + t]);
                al[2] = __float_as_uint(As_lo[r0][ks + t + 4]);
                al[3] = __float_as_uint(As_lo[r0 + 8][ks + t + 4]);
                #pragma unroll
                for (int nt = 0; nt < 4; nt++) {
                    mma_tf32(acc[mt][nt], ah, bh[nt]);
                    mma_tf32(acc[mt][nt], ah, bl[nt]);
                    mma_tf32(acc[mt][nt], al, bh[nt]);
                }
            }
        }
        __syncthreads();
    }

    // ---- epilogue: ReLU + float2 stores ----
    #pragma unroll
    for (int mt = 0; mt < 4; mt++) {
        const int row0 = m_base + wm * 64 + mt * 16 + g;
        const int row1 = row0 + 8;
        #pragma unroll
        for (int nt = 0; nt < 4; nt++) {
            const int col = bcol * BN + wn * 32 + nt * 8 + 2 * t;
            if (row0 < M) {
                float2 v = make_float2(fmaxf(acc[mt][nt][0], 0.f),
                                       fmaxf(acc[mt][nt][1], 0.f));
                *(float2*)(C + (long long)row0 * D + col) = v;
            }
            if (row1 < M) {
                float2 v = make_float2(fmaxf(acc[mt][nt][2], 0.f),
                                       fmaxf(acc[mt][nt][3], 0.f));
                *(float2*)(C + (long long)row1 * D + col) = v;
            }
        }
    }
}

// ---------------------------------------------------------------------------
extern "C" void kernel_launch(void* const* d_in, const int* in_sizes, int n_in,
                              void* d_out, int out_size)
{
    const float* h   = (const float*)d_in[0];
    const float* W   = (const float*)d_in[1];
    const float* ew  = (const float*)d_in[2];
    const void*  src = d_in[3];
    const void*  dst = d_in[4];
    float* out = (float*)d_out;

    const int M = in_sizes[0] / D;   // nodes
    const int E = in_sizes[2];       // edges (ew is unambiguous f32)

    // (d) detect whether src/dst are int32 or int64
    detect_kernel<<<1, 512>>>(src, E);

    // (0) zero histogram
    zero_counts_kernel<<<(M + 255) / 256, 256>>>(M);

    // (1) histogram of dst
    hist_kernel<<<1184, 256>>>(dst, E);

    // (2) 3-phase parallel scan -> offsets + cursors
    const int nchunks = (M + SCAN_CHUNK - 1) / SCAN_CHUNK;   // 25
    scan_block_kernel<<<nchunks, 1024>>>(M);
    scan_tops_kernel<<<1, 32>>>(nchunks);
    scan_add_kernel<<<(M + 1023) / 1024, 1024>>>(M, E);

    // (3) permute edges into CSR-by-dst
    permute_kernel<<<1184, 256>>>(ew, src, dst, E);

    // split W into tf32 hi/lo (overlaps nothing, ~1MB)
    wsplit_kernel<<<(D * D + 255) / 256, 256>>>(W);

    // (4) column-tiled gather-reduce
    dim3 ggrid2((M + 7) / 8, 4);
    gather_kernel<<<ggrid2, 256>>>(h, M);

    // (5) out = relu(g_agg @ W) — 3xTF32 tensor cores, writes every element
    dim3 ggrid(D / BN, (M + BM - 1) / BM);
    gemm_relu_kernel<<<ggrid, 256>>>(out, M);
}

// round 9
// speedup vs baseline: 1.0450x; 1.0031x over previous
#include <cuda_runtime.h>
#include <cuda_bf16.h>
#include <cstdint>

// ---------------------------------------------------------------------------
// EvolveGCNLayer: out = relu(segment_sum( (h@W)[src] * ew , dst ))
// Linearity: segment_sum((h@W)[src]*ew,dst) == segment_sum(h[src]*ew,dst) @ W
// Pipeline (3 launches):
//   (1) preprocess (persistent, grid barriers): detect dtype, zero hist,
//       split W -> tf32 hi/lo, histogram dst, scan -> CSR, permute edges
//   (2) column-tiled gather-reduce (h L2-resident per tile)
//   (3) 3xTF32 tensor-core GEMM g_agg @ W -> out, ReLU fused
// ---------------------------------------------------------------------------

#define D 512
#define MAX_NODES 100000
#define MAX_EDGES 1600000
#define SCAN_CHUNK 4096

__device__ float g_agg[(size_t)MAX_NODES * D];     // aggregated features
__device__ int   g_count[MAX_NODES];               // histogram
__device__ int   g_cursor[MAX_NODES];              // scatter cursors
__device__ int   g_offset[MAX_NODES + 1];          // CSR offsets
__device__ unsigned long long g_pedge[MAX_EDGES];  // packed (src | ew<<32)
__device__ int   g_idx_is64;                       // 1 if src/dst are int64
__device__ int   g_bsum[64];                       // per-chunk scan sums
__device__ float g_Wh[D * D];                      // W split: tf32 hi
__device__ float g_Wl[D * D];                      // W split: tf32 lo
__device__ unsigned g_bar_count;                   // grid barrier state
__device__ unsigned g_bar_gen;

// ---------------------- tf32 split helper ----------------------------------
__device__ __forceinline__ void split_tf32(float x, float& hi, float& lo) {
    unsigned hbits, lbits;
    asm("cvt.rna.tf32.f32 %0, %1;" : "=r"(hbits) : "f"(x));
    float hf = __uint_as_float(hbits);
    float r = x - hf;                       // exact in fp32
    asm("cvt.rna.tf32.f32 %0, %1;" : "=r"(lbits) : "f"(r));
    hi = hf;
    lo = __uint_as_float(lbits);
}

__device__ __forceinline__ int load_idx(const void* p, int i, int is64) {
    return is64 ? (int)((const long long*)p)[i] : ((const int*)p)[i];
}

// ---------------------- grid-wide barrier (persistent kernel) --------------
// All blocks co-resident: __launch_bounds__(256,4) caps regs at 64; 592
// blocks = 148 SMs x 4 (GB300 has 152 SMs). Count self-resets; gen monotone.
__device__ __forceinline__ void grid_barrier() {
    __syncthreads();
    if (threadIdx.x == 0) {
        __threadfence();
        unsigned gen = atomicAdd(&g_bar_gen, 0u);
        if (atomicAdd(&g_bar_count, 1u) == gridDim.x - 1) {
            g_bar_count = 0;
            __threadfence();
            atomicAdd(&g_bar_gen, 1u);
        } else {
            while (atomicAdd(&g_bar_gen, 0u) == gen) { __nanosleep(64); }
        }
        __threadfence();
    }
    __syncthreads();
}

// ---------------------- (1) fused preprocessing ----------------------------
#define PP_BLOCKS 592

__global__ __launch_bounds__(256, 4) void preprocess_kernel(
    const float* __restrict__ W,
    const float* __restrict__ ew,
    const void*  __restrict__ src,
    const void*  __restrict__ dst,
    int M, int E, int nchunks)
{
    __shared__ int sm_ws[8];
    __shared__ int sm_boff[64];

    const int tid     = threadIdx.x;
    const int gtid    = blockIdx.x * 256 + tid;
    const int gstride = gridDim.x * 256;

    // ---- phase 0: detect dtype (block 0) + zero hist + split W ----
    if (blockIdx.x == 0) {
        const unsigned long long* p = (const unsigned long long*)src;
        int n = E / 2; if (n > 512) n = 512;
        int bad = 0;
        for (int i = tid; i < n; i += 256)
            if (p[i] >= 4294967296ULL) bad = 1;
        bad = __syncthreads_or(bad);
        if (tid == 0) g_idx_is64 = bad ? 0 : 1;
    }
    for (int i = gtid; i < M; i += gstride) g_count[i] = 0;
    for (int i = gtid; i < D * D; i += gstride) {
        float hi, lo;
        split_tf32(W[i], hi, lo);
        g_Wh[i] = hi;
        g_Wl[i] = lo;
    }
    grid_barrier();

    const int is64 = g_idx_is64;

    // ---- phase 1: histogram of dst ----
    for (int i = gtid; i < E; i += gstride)
        atomicAdd(&g_count[load_idx(dst, i, is64)], 1);
    grid_barrier();

    // ---- phase 2a: local scan per 4096-chunk (blocks 0..nchunks-1) ----
    if (blockIdx.x < nchunks) {
        const int lane = tid & 31;
        const int wid  = tid >> 5;
        const int base = blockIdx.x * SCAN_CHUNK + tid * 16;

        int v[16];
        #pragma unroll
        for (int q = 0; q < 4; q++) {
            const int idx = base + q * 4;
            if (idx + 3 < M) {
                int4 t = *(const int4*)&g_count[idx];
                v[q*4+0] = t.x; v[q*4+1] = t.y; v[q*4+2] = t.z; v[q*4+3] = t.w;
            } else {
                #pragma unroll
                for (int r = 0; r < 4; r++)
                    v[q*4+r] = (idx + r < M) ? g_count[idx + r] : 0;
            }
        }
        int tsum = 0;
        #pragma unroll
        for (int q = 0; q < 16; q++) tsum += v[q];

        int s = tsum;
        #pragma unroll
        for (int off = 1; off < 32; off <<= 1) {
            int t = __shfl_up_sync(0xffffffffu, s, off);
            if (lane >= off) s += t;
        }
        if (lane == 31) sm_ws[wid] = s;
        __syncthreads();
        if (wid == 0 && lane < 8) {
            int ws = sm_ws[lane];
            #pragma unroll
            for (int off = 1; off < 8; off <<= 1) {
                int t = __shfl_up_sync(0x000000ffu, ws, off);
                if (lane >= off) ws += t;
            }
            sm_ws[lane] = ws;
        }
        __syncthreads();

        int running = ((wid > 0) ? sm_ws[wid - 1] : 0) + s - tsum;
        #pragma unroll
        for (int q = 0; q < 16; q++) {
            if (base + q < M) g_offset[base + q] = running;
            running += v[q];
        }
        if (tid == 0) g_bsum[blockIdx.x] = sm_ws[7];
        __syncthreads();
    }
    grid_barrier();

    // ---- phase 2b: add chunk offsets, emit cursors + sentinel ----
    if (tid == 0) {
        int run = 0;
        for (int c = 0; c < nchunks; c++) { sm_boff[c] = run; run += g_bsum[c]; }
    }
    __syncthreads();
    for (int i = gtid; i < M; i += gstride) {
        const int o = g_offset[i] + sm_boff[i >> 12];
        g_offset[i] = o;
        g_cursor[i] = o;
    }
    if (gtid == 0) g_offset[M] = E;
    grid_barrier();

    // ---- phase 3: permute edges into CSR order (packed 8B records) ----
    for (int i = gtid; i < E; i += gstride) {
        const int d = load_idx(dst, i, is64);
        const int pos = atomicAdd(&g_cursor[d], 1);
        const unsigned sv = (unsigned)load_idx(src, i, is64);
        const unsigned wv = __float_as_uint(ew[i]);
        g_pedge[pos] = (unsigned long long)sv |
                       ((unsigned long long)wv << 32);
    }
}

// ---------------------- (2) column-tiled gather-reduce ---------------------
// D tiled into 4 slices of 128 floats; per-pass h working set 51.2MB (L2-
// resident; grid sweeps x-fastest so one tile's wave completes before the
// next tile begins). One warp per (node, tile); lane owns one float4.
__global__ __launch_bounds__(256) void gather_kernel(
    const float* __restrict__ h, int n_nodes)
{
    const int warp_in_blk = threadIdx.x >> 5;
    const int lane        = threadIdx.x & 31;
    const int node        = blockIdx.x * 8 + warp_in_blk;
    const int tile        = blockIdx.y;              // 0..3
    if (node >= n_nodes) return;

    const int beg = g_offset[node];
    const int end = g_offset[node + 1];

    const float4* __restrict__ h4 = (const float4*)h + tile * 32 + lane;

    float4 a0 = make_float4(0.f, 0.f, 0.f, 0.f);
    float4 a1 = make_float4(0.f, 0.f, 0.f, 0.f);
    float4 a2 = make_float4(0.f, 0.f, 0.f, 0.f);
    float4 a3 = make_float4(0.f, 0.f, 0.f, 0.f);

    int j = beg;
    for (; j + 3 < end; j += 4) {
        const unsigned long long e0 = g_pedge[j],     e1 = g_pedge[j + 1];
        const unsigned long long e2 = g_pedge[j + 2], e3 = g_pedge[j + 3];
        const float w0 = __uint_as_float((unsigned)(e0 >> 32));
        const float w1 = __uint_as_float((unsigned)(e1 >> 32));
        const float w2 = __uint_as_float((unsigned)(e2 >> 32));
        const float w3 = __uint_as_float((unsigned)(e3 >> 32));
        float4 v0 = h4[(long long)(unsigned)e0 * 128];
        float4 v1 = h4[(long long)(unsigned)e1 * 128];
        float4 v2 = h4[(long long)(unsigned)e2 * 128];
        float4 v3 = h4[(long long)(unsigned)e3 * 128];
        a0.x += v0.x * w0; a0.y += v0.y * w0; a0.z += v0.z * w0; a0.w += v0.w * w0;
        a1.x += v1.x * w1; a1.y += v1.y * w1; a1.z += v1.z * w1; a1.w += v1.w * w1;
        a2.x += v2.x * w2; a2.y += v2.y * w2; a2.z += v2.z * w2; a2.w += v2.w * w2;
        a3.x += v3.x * w3; a3.y += v3.y * w3; a3.z += v3.z * w3; a3.w += v3.w * w3;
    }
    for (; j < end; j++) {
        const unsigned long long e = g_pedge[j];
        const float w = __uint_as_float((unsigned)(e >> 32));
        float4 v = h4[(long long)(unsigned)e * 128];
        a0.x += v.x * w; a0.y += v.y * w; a0.z += v.z * w; a0.w += v.w * w;
    }
    a0.x += a1.x + a2.x + a3.x;
    a0.y += a1.y + a2.y + a3.y;
    a0.z += a1.z + a2.z + a3.z;
    a0.w += a1.w + a2.w + a3.w;

    ((float4*)g_agg)[(long long)node * 128 + tile * 32 + lane] = a0;
}

// ---------------------- (3) 3xTF32 tensor GEMM + fused ReLU ----------------
// C = relu(g_agg @ W). BM=128, BN=128, BK=16. 8 warps (2x4), warp tile 64x32,
// mma.m16n8k8 tf32. D = Ah*Bh + Ah*Bl + Al*Bh. Register-prefetch pipelining.
#define BM 128
#define BN 128
#define BK 16
#define ASTR 20     // bank=(20g+t)%32 all distinct
#define BSTR 136    // bank=(8t+g)%32 all distinct

__device__ __forceinline__ void mma_tf32(float* c, const unsigned* a,
                                         const unsigned* b) {
    asm volatile(
        "mma.sync.aligned.m16n8k8.row.col.f32.tf32.tf32.f32 "
        "{%0,%1,%2,%3}, {%4,%5,%6,%7}, {%8,%9}, {%0,%1,%2,%3};"
        : "+f"(c[0]), "+f"(c[1]), "+f"(c[2]), "+f"(c[3])
        : "r"(a[0]), "r"(a[1]), "r"(a[2]), "r"(a[3]),
          "r"(b[0]), "r"(b[1]));
}

__global__ __launch_bounds__(256) void gemm_relu_kernel(
    float* __restrict__ C,         // out [M, 512]
    int M)
{
    __shared__ float As_hi[BM][ASTR], As_lo[BM][ASTR];
    __shared__ float Bs_hi[BK][BSTR], Bs_lo[BK][BSTR];

    const int bcol   = blockIdx.x;         // 0..3
    const int m_base = blockIdx.y * BM;
    const int tid    = threadIdx.x;
    const int wid    = tid >> 5;
    const int lane   = tid & 31;
    const int g      = lane >> 2;          // groupID 0..7
    const int t      = lane & 3;           // threadInGroup 0..3

    const int wm = wid & 1;                // 64-row half
    const int wn = wid >> 1;               // 32-col strip

    const float* Ab  = g_agg + (long long)m_base * D;
    const float* Bbh = g_Wh + bcol * BN;
    const float* Bbl = g_Wl + bcol * BN;

    // loader mappings
    const int a_row0 = tid >> 2;           // 0..63  (two iters: +64)
    const int a_c4   = (tid & 3) * 4;      // 0,4,8,12
    const int b_row0 = tid >> 5;           // 0..7   (two iters: +8)
    const int b_c4   = (tid & 31) * 4;     // 0..124

    float acc[4][4][4];
    #pragma unroll
    for (int i = 0; i < 4; i++)
        #pragma unroll
        for (int j = 0; j < 4; j++)
            #pragma unroll
            for (int r = 0; r < 4; r++) acc[i][j][r] = 0.0f;

    // ---- preload k0 = 0 tile ----
    float4 pa[2], pbh[2], pbl[2];
    #pragma unroll
    for (int it = 0; it < 2; it++) {
        const int row = a_row0 + it * 64;
        pa[it] = make_float4(0.f, 0.f, 0.f, 0.f);
        if (m_base + row < M)
            pa[it] = *(const float4*)(Ab + (long long)row * D + a_c4);
        const long long boff = (long long)(b_row0 + it * 8) * D + b_c4;
        pbh[it] = *(const float4*)(Bbh + boff);
        pbl[it] = *(const float4*)(Bbl + boff);
    }

    for (int k0 = 0; k0 < D; k0 += BK) {
        // ---- store staged tile to smem ----
        #pragma unroll
        for (int it = 0; it < 2; it++) {
            const int row = a_row0 + it * 64;
            float h0, l0, h1, l1, h2, l2, h3, l3;
            split_tf32(pa[it].x, h0, l0); split_tf32(pa[it].y, h1, l1);
            split_tf32(pa[it].z, h2, l2); split_tf32(pa[it].w, h3, l3);
            *(float4*)&As_hi[row][a_c4] = make_float4(h0, h1, h2, h3);
            *(float4*)&As_lo[row][a_c4] = make_float4(l0, l1, l2, l3);
            const int brow = b_row0 + it * 8;
            *(float4*)&Bs_hi[brow][b_c4] = pbh[it];
            *(float4*)&Bs_lo[brow][b_c4] = pbl[it];
        }
        __syncthreads();

        // ---- prefetch next tile into registers (overlaps with MMA) ----
        if (k0 + BK < D) {
            const int kn = k0 + BK;
            #pragma unroll
            for (int it = 0; it < 2; it++) {
                const int row = a_row0 + it * 64;
                pa[it] = make_float4(0.f, 0.f, 0.f, 0.f);
                if (m_base + row < M)
                    pa[it] = *(const float4*)(Ab + (long long)row * D + kn + a_c4);
                const long long boff = (long long)(kn + b_row0 + it * 8) * D + b_c4;
                pbh[it] = *(const float4*)(Bbh + boff);
                pbl[it] = *(const float4*)(Bbl + boff);
            }
        }

        // ---- two k-steps of 8 ----
        #pragma unroll
        for (int ks = 0; ks < BK; ks += 8) {
            unsigned bh[4][2], bl[4][2];
            #pragma unroll
            for (int nt = 0; nt < 4; nt++) {
                const int n = wn * 32 + nt * 8 + g;
                bh[nt][0] = __float_as_uint(Bs_hi[ks + t][n]);
                bh[nt][1] = __float_as_uint(Bs_hi[ks + t + 4][n]);
                bl[nt][0] = __float_as_uint(Bs_lo[ks + t][n]);
                bl[nt][1] = __float_as_uint(Bs_lo[ks + t + 4][n]);
            }
            #pragma unroll
            for (int mt = 0; mt < 4; mt++) {
                const int r0 = wm * 64 + mt * 16 + g;
                unsigned ah[4], al[4];
                ah[0] = __float_as_uint(As_hi[r0][ks + t]);
                ah[1] = __float_as_uint(As_hi[r0 + 8][ks + t]);
                ah[2] = __float_as_uint(As_hi[r0][ks + t + 4]);
                ah[3] = __float_as_uint(As_hi[r0 + 8][ks + t + 4]);
                al[0] = __float_as_uint(As_lo[r0][ks + t]);
                al[1] = __float_as_uint(As_lo[r0 + 8][ks + t]);
                al[2] = __float_as_uint(As_lo[r0][ks + t + 4]);
                al[3] = __float_as_uint(As_lo[r0 + 8][ks + t + 4]);
                #pragma unroll
                for (int nt = 0; nt < 4; nt++) {
                    mma_tf32(acc[mt][nt], ah, bh[nt]);
                    mma_tf32(acc[mt][nt], ah, bl[nt]);
                    mma_tf32(acc[mt][nt], al, bh[nt]);
                }
            }
        }
        __syncthreads();
    }

    // ---- epilogue: ReLU + float2 stores ----
    #pragma unroll
    for (int mt = 0; mt < 4; mt++) {
        const int row0 = m_base + wm * 64 + mt * 16 + g;
        const int row1 = row0 + 8;
        #pragma unroll
        for (int nt = 0; nt < 4; nt++) {
            const int col = bcol * BN + wn * 32 + nt * 8 + 2 * t;
            if (row0 < M) {
                float2 v = make_float2(fmaxf(acc[mt][nt][0], 0.f),
                                       fmaxf(acc[mt][nt][1], 0.f));
                *(float2*)(C + (long long)row0 * D + col) = v;
            }
            if (row1 < M) {
                float2 v = make_float2(fmaxf(acc[mt][nt][2], 0.f),
                                       fmaxf(acc[mt][nt][3], 0.f));
                *(float2*)(C + (long long)row1 * D + col) = v;
            }
        }
    }
}

// ---------------------------------------------------------------------------
extern "C" void kernel_launch(void* const* d_in, const int* in_sizes, int n_in,
                              void* d_out, int out_size)
{
    const float* h   = (const float*)d_in[0];
    const float* W   = (const float*)d_in[1];
    const float* ew  = (const float*)d_in[2];
    const void*  src = d_in[3];
    const void*  dst = d_in[4];
    float* out = (float*)d_out;

    const int M = in_sizes[0] / D;   // nodes
    const int E = in_sizes[2];       // edges (ew is unambiguous f32)
    const int nchunks = (M + SCAN_CHUNK - 1) / SCAN_CHUNK;   // 25

    // (1) fused preprocessing (persistent kernel, grid barriers)
    preprocess_kernel<<<PP_BLOCKS, 256>>>(W, ew, src, dst, M, E, nchunks);

    // (2) column-tiled gather-reduce
    dim3 ggrid2((M + 7) / 8, 4);
    gather_kernel<<<ggrid2, 256>>>(h, M);

    // (3) out = relu(g_agg @ W) — 3xTF32 tensor cores, writes every element
    dim3 ggrid(D / BN, (M + BM - 1) / BM);
    gemm_relu_kernel<<<ggrid, 256>>>(out, M);
}

// round 17
// speedup vs baseline: 1.6190x; 1.5493x over previous
#include <cuda_runtime.h>
#include <cuda_bf16.h>
#include <cstdint>

// ---------------------------------------------------------------------------
// EvolveGCNLayer: out = relu(segment_sum( (h@W)[src] * ew , dst ))
// Linearity: segment_sum((h@W)[src]*ew,dst) == segment_sum(h[src]*ew,dst) @ W
// Pipeline (4 launches):
//   (1) preprocess (persistent, grid barriers): detect dtype, zero hist,
//       split W -> packed bf16x2 hi/lo, histogram dst, scan -> CSR, permute
//   (2a/2b) column-tiled gather-reduce, tiles {0,1} then {2,3}
//   (3) 3xBF16 split-precision tensor GEMM g_agg @ W -> out, ReLU fused
//       D = Ah*Bh + Ah*Bl + Al*Bh   (Al*Bl ~ 2^-18, dropped)
// ---------------------------------------------------------------------------

#define D 512
#define MAX_NODES 100000
#define MAX_EDGES 1600000
#define SCAN_CHUNK 4096

__device__ float g_agg[(size_t)MAX_NODES * D];     // aggregated features
__device__ int   g_count[MAX_NODES];               // histogram
__device__ int   g_cursor[MAX_NODES];              // scatter cursors
__device__ int   g_offset[MAX_NODES + 1];          // CSR offsets
__device__ unsigned long long g_pedge[MAX_EDGES];  // packed (src | ew<<32)
__device__ int   g_idx_is64;                       // 1 if src/dst are int64
__device__ int   g_bsum[64];                       // per-chunk scan sums
__device__ unsigned g_Wph[D * D / 2];              // W hi: bf16x2 [k/2][n]
__device__ unsigned g_Wpl[D * D / 2];              // W lo: bf16x2 [k/2][n]
__device__ unsigned g_bar_count;                   // grid barrier state
__device__ unsigned g_bar_gen;

// ---------------------- bf16 split helpers ---------------------------------
__device__ __forceinline__ unsigned bf16pair(float a, float b) {
    // a -> low 16 bits (even k), b -> high 16 bits (odd k)
    __nv_bfloat162 p = __floats2bfloat162_rn(a, b);
    return *(unsigned*)&p;
}

__device__ __forceinline__ float bf16_round(float x) {
    __nv_bfloat16 b = __float2bfloat16(x);
    return __bfloat162float(b);
}

__device__ __forceinline__ int load_idx(const void* p, int i, int is64) {
    return is64 ? (int)((const long long*)p)[i] : ((const int*)p)[i];
}

// ---------------------- grid-wide barrier (persistent kernel) --------------
// All blocks co-resident: __launch_bounds__(256,4) caps regs at 64; 592
// blocks = 148 SMs x 4 (GB300 has 152 SMs). Count self-resets; gen monotone.
__device__ __forceinline__ void grid_barrier() {
    __syncthreads();
    if (threadIdx.x == 0) {
        __threadfence();
        unsigned gen = atomicAdd(&g_bar_gen, 0u);
        if (atomicAdd(&g_bar_count, 1u) == gridDim.x - 1) {
            g_bar_count = 0;
            __threadfence();
            atomicAdd(&g_bar_gen, 1u);
        } else {
            while (atomicAdd(&g_bar_gen, 0u) == gen) { __nanosleep(64); }
        }
        __threadfence();
    }
    __syncthreads();
}

// ---------------------- (1) fused preprocessing ----------------------------
#define PP_BLOCKS 592

__global__ __launch_bounds__(256, 4) void preprocess_kernel(
    const float* __restrict__ W,
    const float* __restrict__ ew,
    const void*  __restrict__ src,
    const void*  __restrict__ dst,
    int M, int E, int nchunks)
{
    __shared__ int sm_ws[8];
    __shared__ int sm_boff[64];

    const int tid     = threadIdx.x;
    const int gtid    = blockIdx.x * 256 + tid;
    const int gstride = gridDim.x * 256;

    // ---- phase 0: detect dtype (block 0) + zero hist + split W ----
    if (blockIdx.x == 0) {
        const unsigned long long* p = (const unsigned long long*)src;
        int n = E / 2; if (n > 512) n = 512;
        int bad = 0;
        for (int i = tid; i < n; i += 256)
            if (p[i] >= 4294967296ULL) bad = 1;
        bad = __syncthreads_or(bad);
        if (tid == 0) g_idx_is64 = bad ? 0 : 1;
    }
    for (int i = gtid; i < M; i += gstride) g_count[i] = 0;
    // split W into packed bf16x2 hi/lo: g_Wp[kp*D + n] packs (k=2kp, k=2kp+1)
    for (int i = gtid; i < D * D / 2; i += gstride) {
        const int kp = i / D;
        const int n  = i - kp * D;
        const float w0 = W[(2 * kp) * D + n];
        const float w1 = W[(2 * kp + 1) * D + n];
        const float h0 = bf16_round(w0), h1 = bf16_round(w1);
        g_Wph[i] = bf16pair(h0, h1);
        g_Wpl[i] = bf16pair(w0 - h0, w1 - h1);
    }
    grid_barrier();

    const int is64 = g_idx_is64;

    // ---- phase 1: histogram of dst ----
    for (int i = gtid; i < E; i += gstride)
        atomicAdd(&g_count[load_idx(dst, i, is64)], 1);
    grid_barrier();

    // ---- phase 2a: local scan per 4096-chunk (blocks 0..nchunks-1) ----
    if (blockIdx.x < nchunks) {
        const int lane = tid & 31;
        const int wid  = tid >> 5;
        const int base = blockIdx.x * SCAN_CHUNK + tid * 16;

        int v[16];
        #pragma unroll
        for (int q = 0; q < 4; q++) {
            const int idx = base + q * 4;
            if (idx + 3 < M) {
                int4 t = *(const int4*)&g_count[idx];
                v[q*4+0] = t.x; v[q*4+1] = t.y; v[q*4+2] = t.z; v[q*4+3] = t.w;
            } else {
                #pragma unroll
                for (int r = 0; r < 4; r++)
                    v[q*4+r] = (idx + r < M) ? g_count[idx + r] : 0;
            }
        }
        int tsum = 0;
        #pragma unroll
        for (int q = 0; q < 16; q++) tsum += v[q];

        int s = tsum;
        #pragma unroll
        for (int off = 1; off < 32; off <<= 1) {
            int t = __shfl_up_sync(0xffffffffu, s, off);
            if (lane >= off) s += t;
        }
        if (lane == 31) sm_ws[wid] = s;
        __syncthreads();
        if (wid == 0 && lane < 8) {
            int ws = sm_ws[lane];
            #pragma unroll
            for (int off = 1; off < 8; off <<= 1) {
                int t = __shfl_up_sync(0x000000ffu, ws, off);
                if (lane >= off) ws += t;
            }
            sm_ws[lane] = ws;
        }
        __syncthreads();

        int running = ((wid > 0) ? sm_ws[wid - 1] : 0) + s - tsum;
        #pragma unroll
        for (int q = 0; q < 16; q++) {
            if (base + q < M) g_offset[base + q] = running;
            running += v[q];
        }
        if (tid == 0) g_bsum[blockIdx.x] = sm_ws[7];
        __syncthreads();
    }
    grid_barrier();

    // ---- phase 2b: add chunk offsets, emit cursors + sentinel ----
    if (tid == 0) {
        int run = 0;
        for (int c = 0; c < nchunks; c++) { sm_boff[c] = run; run += g_bsum[c]; }
    }
    __syncthreads();
    for (int i = gtid; i < M; i += gstride) {
        const int o = g_offset[i] + sm_boff[i >> 12];
        g_offset[i] = o;
        g_cursor[i] = o;
    }
    if (gtid == 0) g_offset[M] = E;
    grid_barrier();

    // ---- phase 3: permute edges into CSR order (packed 8B records) ----
    for (int i = gtid; i < E; i += gstride) {
        const int d = load_idx(dst, i, is64);
        const int pos = atomicAdd(&g_cursor[d], 1);
        const unsigned sv = (unsigned)load_idx(src, i, is64);
        const unsigned wv = __float_as_uint(ew[i]);
        g_pedge[pos] = (unsigned long long)sv |
                       ((unsigned long long)wv << 32);
    }
}

// ---------------------- (2) column-tiled gather-reduce ---------------------
// D tiled into 4 slices of 128 floats; per-pass h working set 51.2MB (L2-
// resident). Two launches of 2 tiles each. One warp per (node, tile); lane
// owns one float4; 8-deep edge unroll for MLP=8 latency hiding.
__global__ __launch_bounds__(256) void gather_kernel(
    const float* __restrict__ h, int n_nodes, int tile_base)
{
    const int warp_in_blk = threadIdx.x >> 5;
    const int lane        = threadIdx.x & 31;
    const int node        = blockIdx.x * 8 + warp_in_blk;
    const int tile        = tile_base + blockIdx.y;      // 2 tiles per launch
    if (node >= n_nodes) return;

    const int beg = g_offset[node];
    const int end = g_offset[node + 1];

    const float4* __restrict__ h4 = (const float4*)h + tile * 32 + lane;

    float4 a0 = make_float4(0.f, 0.f, 0.f, 0.f);
    float4 a1 = make_float4(0.f, 0.f, 0.f, 0.f);
    float4 a2 = make_float4(0.f, 0.f, 0.f, 0.f);
    float4 a3 = make_float4(0.f, 0.f, 0.f, 0.f);

    int j = beg;
    for (; j + 7 < end; j += 8) {
        unsigned long long e[8];
        #pragma unroll
        for (int q = 0; q < 8; q++) e[q] = g_pedge[j + q];
        float4 v[8];
        #pragma unroll
        for (int q = 0; q < 8; q++)
            v[q] = h4[(long long)(unsigned)e[q] * 128];
        #pragma unroll
        for (int q = 0; q < 8; q++) {
            const float w = __uint_as_float((unsigned)(e[q] >> 32));
            float4* acc = (q & 2) ? ((q & 1) ? &a3 : &a2)
                                  : ((q & 1) ? &a1 : &a0);
            acc->x += v[q].x * w; acc->y += v[q].y * w;
            acc->z += v[q].z * w; acc->w += v[q].w * w;
        }
    }
    for (; j < end; j++) {
        const unsigned long long e = g_pedge[j];
        const float w = __uint_as_float((unsigned)(e >> 32));
        float4 v = h4[(long long)(unsigned)e * 128];
        a0.x += v.x * w; a0.y += v.y * w; a0.z += v.z * w; a0.w += v.w * w;
    }
    a0.x += a1.x + a2.x + a3.x;
    a0.y += a1.y + a2.y + a3.y;
    a0.z += a1.z + a2.z + a3.z;
    a0.w += a1.w + a2.w + a3.w;

    ((float4*)g_agg)[(long long)node * 128 + tile * 32 + lane] = a0;
}

// ---------------------- (3) 3xBF16 tensor GEMM + fused ReLU ----------------
// C = relu(g_agg @ W). BM=128, BN=128, BK=16. 8 warps (2x4), warp tile 64x32,
// mma.m16n8k16.bf16 (4096 FLOP/instr, 2x tf32 rate).
// Split precision: X = Xh + Xl (bf16 each); D = Ah*Bh + Ah*Bl + Al*Bh.
#define BM 128
#define BN 128
#define BK 16
#define KP (BK / 2)   // 8 k-pairs per tile
#define ASTR2 12      // uint stride: bank=(12g+t)%32 all 32 distinct
#define BSTR2 136     // uint stride: bank=(8t+g)%32 all 32 distinct

__device__ __forceinline__ void mma_bf16(float* c, const unsigned* a,
                                         const unsigned* b) {
    asm volatile(
        "mma.sync.aligned.m16n8k16.row.col.f32.bf16.bf16.f32 "
        "{%0,%1,%2,%3}, {%4,%5,%6,%7}, {%8,%9}, {%0,%1,%2,%3};"
        : "+f"(c[0]), "+f"(c[1]), "+f"(c[2]), "+f"(c[3])
        : "r"(a[0]), "r"(a[1]), "r"(a[2]), "r"(a[3]),
          "r"(b[0]), "r"(b[1]));
}

__global__ __launch_bounds__(256) void gemm_relu_kernel(
    float* __restrict__ C,         // out [M, 512]
    int M)
{
    __shared__ unsigned Asp_hi[BM][ASTR2], Asp_lo[BM][ASTR2];  // 6KB each
    __shared__ unsigned Bsp_hi[KP][BSTR2], Bsp_lo[KP][BSTR2];  // 4.25KB each

    const int bcol   = blockIdx.x;         // 0..3
    const int m_base = blockIdx.y * BM;
    const int tid    = threadIdx.x;
    const int wid    = tid >> 5;
    const int lane   = tid & 31;
    const int g      = lane >> 2;          // groupID 0..7
    const int t      = lane & 3;           // threadInGroup 0..3

    const int wm = wid & 1;                // 64-row half
    const int wn = wid >> 1;               // 32-col strip

    const float* Ab = g_agg + (long long)m_base * D;

    // loader mappings
    const int a_row0 = tid >> 2;           // 0..63  (two iters: +64)
    const int a_c4   = (tid & 3) * 4;      // k base: 0,4,8,12
    const int b_row0 = tid >> 5;           // kpair 0..7
    const int b_c4   = (tid & 31) * 4;     // n base: 0..124

    float acc[4][4][4];
    #pragma unroll
    for (int i = 0; i < 4; i++)
        #pragma unroll
        for (int j = 0; j < 4; j++)
            #pragma unroll
            for (int r = 0; r < 4; r++) acc[i][j][r] = 0.0f;

    // ---- preload k0 = 0 tile ----
    float4 pa[2];
    uint4  pbh, pbl;
    #pragma unroll
    for (int it = 0; it < 2; it++) {
        const int row = a_row0 + it * 64;
        pa[it] = make_float4(0.f, 0.f, 0.f, 0.f);
        if (m_base + row < M)
            pa[it] = *(const float4*)(Ab + (long long)row * D + a_c4);
    }
    {
        const int off = b_row0 * D + bcol * BN + b_c4;   // [kpair][n]
        pbh = *(const uint4*)(g_Wph + off);
        pbl = *(const uint4*)(g_Wpl + off);
    }

    for (int k0 = 0; k0 < D; k0 += BK) {
        // ---- stage tile: split A to bf16 hi/lo pairs; copy packed B ----
        #pragma unroll
        for (int it = 0; it < 2; it++) {
            const int row = a_row0 + it * 64;
            const float hx = bf16_round(pa[it].x), hy = bf16_round(pa[it].y);
            const float hz = bf16_round(pa[it].z), hw = bf16_round(pa[it].w);
            const int kp = a_c4 >> 1;                    // 0,2,4,6
            Asp_hi[row][kp]     = bf16pair(hx, hy);
            Asp_hi[row][kp + 1] = bf16pair(hz, hw);
            Asp_lo[row][kp]     = bf16pair(pa[it].x - hx, pa[it].y - hy);
            Asp_lo[row][kp + 1] = bf16pair(pa[it].z - hz, pa[it].w - hw);
        }
        *(uint4*)&Bsp_hi[b_row0][b_c4] = pbh;
        *(uint4*)&Bsp_lo[b_row0][b_c4] = pbl;
        __syncthreads();

        // ---- prefetch next tile into registers (overlaps with MMA) ----
        if (k0 + BK < D) {
            const int kn = k0 + BK;
            #pragma unroll
            for (int it = 0; it < 2; it++) {
                const int row = a_row0 + it * 64;
                pa[it] = make_float4(0.f, 0.f, 0.f, 0.f);
                if (m_base + row < M)
                    pa[it] = *(const float4*)(Ab + (long long)row * D + kn + a_c4);
            }
            const int off = (kn / 2 + b_row0) * D + bcol * BN + b_c4;
            pbh = *(const uint4*)(g_Wph + off);
            pbl = *(const uint4*)(g_Wpl + off);
        }

        // ---- one k-step of 16 ----
        {
            unsigned bh[4][2], bl[4][2];
            #pragma unroll
            for (int nt = 0; nt < 4; nt++) {
                const int n = wn * 32 + nt * 8 + g;
                bh[nt][0] = Bsp_hi[t][n];
                bh[nt][1] = Bsp_hi[t + 4][n];
                bl[nt][0] = Bsp_lo[t][n];
                bl[nt][1] = Bsp_lo[t + 4][n];
            }
            #pragma unroll
            for (int mt = 0; mt < 4; mt++) {
                const int r0 = wm * 64 + mt * 16 + g;
                unsigned ah[4], al[4];
                ah[0] = Asp_hi[r0][t];
                ah[1] = Asp_hi[r0 + 8][t];
                ah[2] = Asp_hi[r0][t + 4];
                ah[3] = Asp_hi[r0 + 8][t + 4];
                al[0] = Asp_lo[r0][t];
                al[1] = Asp_lo[r0 + 8][t];
                al[2] = Asp_lo[r0][t + 4];
                al[3] = Asp_lo[r0 + 8][t + 4];
                #pragma unroll
                for (int nt = 0; nt < 4; nt++) {
                    mma_bf16(acc[mt][nt], ah, bh[nt]);
                    mma_bf16(acc[mt][nt], ah, bl[nt]);
                    mma_bf16(acc[mt][nt], al, bh[nt]);
                }
            }
        }
        __syncthreads();
    }

    // ---- epilogue: ReLU + float2 stores ----
    #pragma unroll
    for (int mt = 0; mt < 4; mt++) {
        const int row0 = m_base + wm * 64 + mt * 16 + g;
        const int row1 = row0 + 8;
        #pragma unroll
        for (int nt = 0; nt < 4; nt++) {
            const int col = bcol * BN + wn * 32 + nt * 8 + 2 * t;
            if (row0 < M) {
                float2 v = make_float2(fmaxf(acc[mt][nt][0], 0.f),
                                       fmaxf(acc[mt][nt][1], 0.f));
                *(float2*)(C + (long long)row0 * D + col) = v;
            }
            if (row1 < M) {
                float2 v = make_float2(fmaxf(acc[mt][nt][2], 0.f),
                                       fmaxf(acc[mt][nt][3], 0.f));
                *(float2*)(C + (long long)row1 * D + col) = v;
            }
        }
    }
}

// ---------------------------------------------------------------------------
extern "C" void kernel_launch(void* const* d_in, const int* in_sizes, int n_in,
                              void* d_out, int out_size)
{
    const float* h   = (const float*)d_in[0];
    const float* W   = (const float*)d_in[1];
    const float* ew  = (const float*)d_in[2];
    const void*  src = d_in[3];
    const void*  dst = d_in[4];
    float* out = (float*)d_out;

    const int M = in_sizes[0] / D;   // nodes
    const int E = in_sizes[2];       // edges (ew is unambiguous f32)
    const int nchunks = (M + SCAN_CHUNK - 1) / SCAN_CHUNK;   // 25

    // (1) fused preprocessing (persistent kernel, grid barriers)
    preprocess_kernel<<<PP_BLOCKS, 256>>>(W, ew, src, dst, M, E, nchunks);

    // (2a/2b) column-tiled gather-reduce, 2 tiles per launch
    dim3 ggrid2((M + 7) / 8, 2);
    gather_kernel<<<ggrid2, 256>>>(h, M, 0);
    gather_kernel<<<ggrid2, 256>>>(h, M, 2);

    // (3) out = relu(g_agg @ W) — 3xBF16 split tensor GEMM
    dim3 ggrid(D / BN, (M + BM - 1) / BM);
    gemm_relu_kernel<<<ggrid, 256>>>(out, M);
}